// round 1
// baseline (speedup 1.0000x reference)
#include <cuda_runtime.h>

#define Bz  2
#define T_  2048
#define BT  4096
#define D_  1024
#define H_  16
#define HD_ 64
#define L_  4
#define V_  32000
#define FF_ 4096

// ---------------- scratch (static device memory; no allocations) ----------
__device__ float g_x [BT * D_];
__device__ float g_h [BT * D_];
__device__ float g_q [BT * D_];
__device__ float g_k [BT * D_];
__device__ float g_v [BT * D_];
__device__ float g_ao[BT * D_];
__device__ float g_ff[BT * FF_];

// ---------------- embedding ----------------------------------------------
__global__ void embed_kernel(const int* __restrict__ ctx,
                             const float4* __restrict__ tok,
                             const float4* __restrict__ pos)
{
    int i   = blockIdx.x * 256 + threadIdx.x;   // over BT*D/4
    int row = i / (D_ / 4);
    int c   = i - row * (D_ / 4);
    int t   = row & (T_ - 1);
    float4 a = tok[(size_t)ctx[row] * (D_ / 4) + c];
    float4 b = pos[(size_t)t * (D_ / 4) + c];
    ((float4*)g_x)[i] = make_float4(a.x + b.x, a.y + b.y, a.z + b.z, a.w + b.w);
}

// ---------------- layernorm (one block per row, 256 threads) --------------
__global__ void ln_kernel(const float* __restrict__ in,
                          const float* __restrict__ gamma,
                          const float* __restrict__ beta,
                          float* __restrict__ out)
{
    int row = blockIdx.x;
    const float4* r4 = (const float4*)(in + (size_t)row * D_);
    float4 v = r4[threadIdx.x];                 // D/4 = 256 lanes, 1 each
    float s  = v.x + v.y + v.z + v.w;
    float ss = v.x * v.x + v.y * v.y + v.z * v.z + v.w * v.w;
    #pragma unroll
    for (int o = 16; o > 0; o >>= 1) {
        s  += __shfl_xor_sync(0xffffffffu, s,  o);
        ss += __shfl_xor_sync(0xffffffffu, ss, o);
    }
    __shared__ float shs[8], shss[8];
    int w = threadIdx.x >> 5, lane = threadIdx.x & 31;
    if (lane == 0) { shs[w] = s; shss[w] = ss; }
    __syncthreads();
    float ts = 0.f, tss = 0.f;
    #pragma unroll
    for (int i = 0; i < 8; i++) { ts += shs[i]; tss += shss[i]; }
    float mean = ts * (1.0f / D_);
    float var  = tss * (1.0f / D_) - mean * mean;
    float inv  = rsqrtf(var + 1e-5f);
    float4 g  = ((const float4*)gamma)[threadIdx.x];
    float4 bb = ((const float4*)beta)[threadIdx.x];
    float4 o;
    o.x = (v.x - mean) * inv * g.x + bb.x;
    o.y = (v.y - mean) * inv * g.y + bb.y;
    o.z = (v.z - mean) * inv * g.z + bb.z;
    o.w = (v.w - mean) * inv * g.w + bb.w;
    ((float4*)(out + (size_t)row * D_))[threadIdx.x] = o;
}

// ---------------- fp32 tiled GEMM: C = epi(A[M,K] @ W[K,N]) ---------------
// EPI bit0: +bias (per-col), bit1: relu, bit2: +res (elementwise)
#define BM 128
#define BN 128
#define BKK 16

template <int EPI>
__global__ void __launch_bounds__(256)
gemm_kernel(const float* __restrict__ A, const float* __restrict__ W,
            const float* __restrict__ bias, const float* __restrict__ res,
            float* __restrict__ C, int M, int N, int K)
{
    __shared__ float As[BKK][BM];
    __shared__ float Bs[BKK][BN];
    int bn = blockIdx.x * BN;
    int bm = blockIdx.y * BM;
    int tid = threadIdx.x;
    int tx = tid & 15, ty = tid >> 4;
    const int K4 = K >> 2, N4 = N >> 2;

    float acc[8][8];
    #pragma unroll
    for (int i = 0; i < 8; i++)
        #pragma unroll
        for (int j = 0; j < 8; j++) acc[i][j] = 0.f;

    for (int k0 = 0; k0 < K; k0 += BKK) {
        #pragma unroll
        for (int it = 0; it < 2; it++) {               // A tile 128x16 -> transposed
            int idx = tid + it * 256;
            int r = idx >> 2, c = idx & 3;
            float4 f = ((const float4*)A)[(size_t)(bm + r) * K4 + (k0 >> 2) + c];
            As[c * 4 + 0][r] = f.x; As[c * 4 + 1][r] = f.y;
            As[c * 4 + 2][r] = f.z; As[c * 4 + 3][r] = f.w;
        }
        #pragma unroll
        for (int it = 0; it < 2; it++) {               // B tile 16x128
            int idx = tid + it * 256;
            int r = idx >> 5, c = idx & 31;
            float4 f = ((const float4*)W)[(size_t)(k0 + r) * N4 + (bn >> 2) + c];
            *(float4*)(&Bs[r][c * 4]) = f;
        }
        __syncthreads();
        #pragma unroll
        for (int k = 0; k < BKK; k++) {
            float a[8], b[8];
            #pragma unroll
            for (int i = 0; i < 8; i++) a[i] = As[k][ty * 8 + i];
            #pragma unroll
            for (int j = 0; j < 8; j++) b[j] = Bs[k][tx * 8 + j];
            #pragma unroll
            for (int i = 0; i < 8; i++)
                #pragma unroll
                for (int j = 0; j < 8; j++)
                    acc[i][j] += a[i] * b[j];
        }
        __syncthreads();
    }

    #pragma unroll
    for (int i = 0; i < 8; i++) {
        int m = bm + ty * 8 + i;
        #pragma unroll
        for (int j = 0; j < 8; j += 4) {
            int n = bn + tx * 8 + j;
            float4 v = make_float4(acc[i][j], acc[i][j + 1], acc[i][j + 2], acc[i][j + 3]);
            if (EPI & 1) {
                v.x += bias[n];     v.y += bias[n + 1];
                v.z += bias[n + 2]; v.w += bias[n + 3];
            }
            if (EPI & 2) {
                v.x = fmaxf(v.x, 0.f); v.y = fmaxf(v.y, 0.f);
                v.z = fmaxf(v.z, 0.f); v.w = fmaxf(v.w, 0.f);
            }
            if (EPI & 4) {
                float4 r = ((const float4*)res)[((size_t)m * N + n) >> 2];
                v.x += r.x; v.y += r.y; v.z += r.z; v.w += r.w;
            }
            ((float4*)C)[((size_t)m * N + n) >> 2] = v;
        }
    }
}

// ---------------- causal flash attention (64x64 tiles, HD=64) -------------
#define APAD 68
#define ATTN_SMEM ((4 * 64 * APAD + 192) * 4)

__global__ void __launch_bounds__(256) attn_kernel()
{
    int qi = blockIdx.x;          // query tile (T/64)
    int h  = blockIdx.y;
    int b  = blockIdx.z;
    extern __shared__ float sm[];
    float* Qs   = sm;                    // [e][r] stride APAD
    float* Ks   = Qs + 64 * APAD;        // [e][c]
    float* Vs   = Ks + 64 * APAD;        // [c][e]
    float* Ss   = Vs + 64 * APAD;        // [r][c]
    float* mrow = Ss + 64 * APAD;        // 64
    float* lrow = mrow + 64;             // 64
    float* arow = lrow + 64;             // 64

    int tid = threadIdx.x;
    int tx = tid & 15, ty = tid >> 4;    // 16x16 thread grid, 4x4 micro

    // load Q (transposed into [e][r])
    for (int i = tid; i < 64 * 64; i += 256) {
        int r = i >> 6, e = i & 63;
        Qs[e * APAD + r] = g_q[(size_t)(b * T_ + (qi << 6) + r) * D_ + h * HD_ + e];
    }
    if (tid < 64) { mrow[tid] = -1e30f; lrow[tid] = 0.f; }

    float o[4][4];
    #pragma unroll
    for (int i = 0; i < 4; i++)
        #pragma unroll
        for (int j = 0; j < 4; j++) o[i][j] = 0.f;

    for (int kt = 0; kt <= qi; kt++) {
        __syncthreads();   // prior iter consumed Ks/Vs/Ss
        for (int i = tid; i < 64 * 64; i += 256) {
            int c = i >> 6, e = i & 63;
            size_t g = (size_t)(b * T_ + (kt << 6) + c) * D_ + h * HD_ + e;
            Ks[e * APAD + c] = g_k[g];
            Vs[c * APAD + e] = g_v[g];
        }
        __syncthreads();

        // S = Q K^T (per-thread 4x4)
        float s[4][4];
        #pragma unroll
        for (int i = 0; i < 4; i++)
            #pragma unroll
            for (int j = 0; j < 4; j++) s[i][j] = 0.f;
        #pragma unroll 8
        for (int e = 0; e < 64; e++) {
            float qv[4], kv[4];
            #pragma unroll
            for (int i = 0; i < 4; i++) qv[i] = Qs[e * APAD + ty * 4 + i];
            #pragma unroll
            for (int j = 0; j < 4; j++) kv[j] = Ks[e * APAD + tx * 4 + j];
            #pragma unroll
            for (int i = 0; i < 4; i++)
                #pragma unroll
                for (int j = 0; j < 4; j++)
                    s[i][j] += qv[i] * kv[j];
        }
        #pragma unroll
        for (int i = 0; i < 4; i++)
            #pragma unroll
            for (int j = 0; j < 4; j++) {
                float val = s[i][j] * 0.125f;   // 1/sqrt(64)
                if (kt == qi && (tx * 4 + j) > (ty * 4 + i)) val = -1e30f;
                Ss[(ty * 4 + i) * APAD + tx * 4 + j] = val;
            }
        __syncthreads();

        // online softmax per row (64 active threads)
        if (tid < 64) {
            int r = tid;
            float mo = mrow[r], mx = mo;
            #pragma unroll 8
            for (int c = 0; c < 64; c++) mx = fmaxf(mx, Ss[r * APAD + c]);
            float alpha = __expf(mo - mx);
            float sum = 0.f;
            #pragma unroll 8
            for (int c = 0; c < 64; c++) {
                float p = __expf(Ss[r * APAD + c] - mx);
                Ss[r * APAD + c] = p;
                sum += p;
            }
            lrow[r] = lrow[r] * alpha + sum;
            mrow[r] = mx;
            arow[r] = alpha;
        }
        __syncthreads();

        // O = O*alpha + P V  (per-thread 4 rows x 4 dims)
        float al[4];
        #pragma unroll
        for (int i = 0; i < 4; i++) al[i] = arow[ty * 4 + i];
        #pragma unroll
        for (int i = 0; i < 4; i++)
            #pragma unroll
            for (int j = 0; j < 4; j++) o[i][j] *= al[i];
        #pragma unroll 8
        for (int c = 0; c < 64; c++) {
            float pv[4], vv[4];
            #pragma unroll
            for (int i = 0; i < 4; i++) pv[i] = Ss[(ty * 4 + i) * APAD + c];
            #pragma unroll
            for (int j = 0; j < 4; j++) vv[j] = Vs[c * APAD + tx * 4 + j];
            #pragma unroll
            for (int i = 0; i < 4; i++)
                #pragma unroll
                for (int j = 0; j < 4; j++)
                    o[i][j] += pv[i] * vv[j];
        }
    }

    // write out: o / l
    #pragma unroll
    for (int i = 0; i < 4; i++) {
        float inv = 1.0f / lrow[ty * 4 + i];
        size_t base = (size_t)(b * T_ + (qi << 6) + ty * 4 + i) * D_ + h * HD_ + tx * 4;
        float4 v = make_float4(o[i][0] * inv, o[i][1] * inv, o[i][2] * inv, o[i][3] * inv);
        *(float4*)(g_ao + base) = v;
    }
}

// ---------------- host side ----------------------------------------------
static void launch_gemm(const float* A, const float* W, const float* bias,
                        const float* res, float* C, int M, int N, int K, int epi)
{
    dim3 grid(N / BN, M / BM), blk(256);
    switch (epi) {
        case 0: gemm_kernel<0><<<grid, blk>>>(A, W, nullptr, nullptr, C, M, N, K); break;
        case 1: gemm_kernel<1><<<grid, blk>>>(A, W, bias,    nullptr, C, M, N, K); break;
        case 3: gemm_kernel<3><<<grid, blk>>>(A, W, bias,    nullptr, C, M, N, K); break;
        case 5: gemm_kernel<5><<<grid, blk>>>(A, W, bias,    res,     C, M, N, K); break;
    }
}

extern "C" void kernel_launch(void* const* d_in, const int* in_sizes, int n_in,
                              void* d_out, int out_size)
{
    const int*   ctx  = (const int*)  d_in[0];
    const float* tok  = (const float*)d_in[1];
    const float* pos  = (const float*)d_in[2];
    const float* Wq   = (const float*)d_in[3];
    const float* Wk   = (const float*)d_in[4];
    const float* Wv   = (const float*)d_in[5];
    const float* Wo   = (const float*)d_in[6];
    const float* bo   = (const float*)d_in[7];
    const float* ln1s = (const float*)d_in[8];
    const float* ln1b = (const float*)d_in[9];
    const float* W1   = (const float*)d_in[10];
    const float* b1   = (const float*)d_in[11];
    const float* W2   = (const float*)d_in[12];
    const float* b2   = (const float*)d_in[13];
    const float* ln2s = (const float*)d_in[14];
    const float* ln2b = (const float*)d_in[15];
    const float* lnfs = (const float*)d_in[16];
    const float* lnfb = (const float*)d_in[17];
    const float* Wout = (const float*)d_in[18];
    const float* bout = (const float*)d_in[19];
    float* out = (float*)d_out;

    float *x, *h, *q, *k, *v, *ao, *ff;
    cudaGetSymbolAddress((void**)&x,  g_x);
    cudaGetSymbolAddress((void**)&h,  g_h);
    cudaGetSymbolAddress((void**)&q,  g_q);
    cudaGetSymbolAddress((void**)&k,  g_k);
    cudaGetSymbolAddress((void**)&v,  g_v);
    cudaGetSymbolAddress((void**)&ao, g_ao);
    cudaGetSymbolAddress((void**)&ff, g_ff);

    cudaFuncSetAttribute(attn_kernel,
                         cudaFuncAttributeMaxDynamicSharedMemorySize, ATTN_SMEM);

    embed_kernel<<<BT * D_ / 1024, 256>>>(ctx, (const float4*)tok, (const float4*)pos);

    for (int l = 0; l < L_; l++) {
        ln_kernel<<<BT, 256>>>(x, ln1s + (size_t)l * D_, ln1b + (size_t)l * D_, h);
        launch_gemm(h, Wq + (size_t)l * D_ * D_, nullptr, nullptr, q, BT, D_, D_, 0);
        launch_gemm(h, Wk + (size_t)l * D_ * D_, nullptr, nullptr, k, BT, D_, D_, 0);
        launch_gemm(h, Wv + (size_t)l * D_ * D_, nullptr, nullptr, v, BT, D_, D_, 0);
        attn_kernel<<<dim3(T_ / 64, H_, Bz), 256, ATTN_SMEM>>>();
        launch_gemm(ao, Wo + (size_t)l * D_ * D_, bo + (size_t)l * D_, x, x, BT, D_, D_, 5);
        ln_kernel<<<BT, 256>>>(x, ln2s + (size_t)l * D_, ln2b + (size_t)l * D_, h);
        launch_gemm(h, W1 + (size_t)l * D_ * FF_, b1 + (size_t)l * FF_, nullptr, ff, BT, FF_, D_, 3);
        launch_gemm(ff, W2 + (size_t)l * FF_ * D_, b2 + (size_t)l * D_, x, x, BT, D_, FF_, 5);
    }
    ln_kernel<<<BT, 256>>>(x, lnfs, lnfb, h);
    launch_gemm(h, Wout, bout, nullptr, out, BT, V_, D_, 1);
}

// round 3
// speedup vs baseline: 1.9611x; 1.9611x over previous
#include <cuda_runtime.h>
#include <cstdint>

#define Bz  2
#define T_  2048
#define BT  4096
#define D_  1024
#define H_  16
#define HD_ 64
#define L_  4
#define V_  32000
#define FF_ 4096

// ---------------- scratch (static device memory; no allocations) ----------
__device__ float g_x [BT * D_];
__device__ float g_h [BT * D_];
__device__ float g_q [BT * D_];
__device__ float g_k [BT * D_];
__device__ float g_v [BT * D_];
__device__ float g_ao[BT * D_];
__device__ float g_ff[BT * FF_];

// ---------------- embedding ----------------------------------------------
__global__ void embed_kernel(const int* __restrict__ ctx,
                             const float4* __restrict__ tok,
                             const float4* __restrict__ pos)
{
    int i   = blockIdx.x * 256 + threadIdx.x;   // over BT*D/4
    int row = i / (D_ / 4);
    int c   = i - row * (D_ / 4);
    int t   = row & (T_ - 1);
    float4 a = tok[(size_t)ctx[row] * (D_ / 4) + c];
    float4 b = pos[(size_t)t * (D_ / 4) + c];
    ((float4*)g_x)[i] = make_float4(a.x + b.x, a.y + b.y, a.z + b.z, a.w + b.w);
}

// ---------------- layernorm (one block per row, 256 threads) --------------
__global__ void ln_kernel(const float* __restrict__ in,
                          const float* __restrict__ gamma,
                          const float* __restrict__ beta,
                          float* __restrict__ out)
{
    int row = blockIdx.x;
    const float4* r4 = (const float4*)(in + (size_t)row * D_);
    float4 v = r4[threadIdx.x];
    float s  = v.x + v.y + v.z + v.w;
    float ss = v.x * v.x + v.y * v.y + v.z * v.z + v.w * v.w;
    #pragma unroll
    for (int o = 16; o > 0; o >>= 1) {
        s  += __shfl_xor_sync(0xffffffffu, s,  o);
        ss += __shfl_xor_sync(0xffffffffu, ss, o);
    }
    __shared__ float shs[8], shss[8];
    int w = threadIdx.x >> 5, lane = threadIdx.x & 31;
    if (lane == 0) { shs[w] = s; shss[w] = ss; }
    __syncthreads();
    float ts = 0.f, tss = 0.f;
    #pragma unroll
    for (int i = 0; i < 8; i++) { ts += shs[i]; tss += shss[i]; }
    float mean = ts * (1.0f / D_);
    float var  = tss * (1.0f / D_) - mean * mean;
    float inv  = rsqrtf(var + 1e-5f);
    float4 g  = ((const float4*)gamma)[threadIdx.x];
    float4 bb = ((const float4*)beta)[threadIdx.x];
    float4 o;
    o.x = (v.x - mean) * inv * g.x + bb.x;
    o.y = (v.y - mean) * inv * g.y + bb.y;
    o.z = (v.z - mean) * inv * g.z + bb.z;
    o.w = (v.w - mean) * inv * g.w + bb.w;
    ((float4*)(out + (size_t)row * D_))[threadIdx.x] = o;
}

// ---------------- TF32 tensor-core GEMM ------------------------------------
// C = epi(A[M,K] @ W[K,N]); EPI bit0:+bias  bit1:relu  bit2:+res
#define GBM 128
#define GBN 128
#define GBK 32
#define AST 128          // As row stride (floats) — with XOR swizzle
#define BST 136          // Bs row stride (floats) — pad for conflict-free frags
#define GEMM_SMEM ((2 * GBK * AST + 2 * GBK * BST) * 4)

__device__ __forceinline__ uint32_t f2tf(float f)
{
    uint32_t r;
    asm("cvt.rna.tf32.f32 %0, %1;" : "=r"(r) : "f"(f));
    return r;
}

__device__ __forceinline__ void mma8(float* c, const uint32_t* a, const uint32_t* b)
{
    asm volatile(
        "mma.sync.aligned.m16n8k8.row.col.f32.tf32.tf32.f32 "
        "{%0,%1,%2,%3}, {%4,%5,%6,%7}, {%8,%9}, {%0,%1,%2,%3};"
        : "+f"(c[0]), "+f"(c[1]), "+f"(c[2]), "+f"(c[3])
        : "r"(a[0]), "r"(a[1]), "r"(a[2]), "r"(a[3]), "r"(b[0]), "r"(b[1]));
}

// A smem swizzle: phys_m = m ^ ((k&3)<<3) ^ ((k>>2)&7)
__device__ __forceinline__ int aswz(int k, int m)
{
    return m ^ ((k & 3) << 3) ^ ((k >> 2) & 7);
}

template <int EPI>
__global__ void __launch_bounds__(256)
gemm_tc(const float* __restrict__ A, const float* __restrict__ W,
        const float* __restrict__ bias, const float* __restrict__ res,
        float* __restrict__ C, int M, int N, int K)
{
    extern __shared__ uint32_t smu[];
    uint32_t (*As)[GBK][AST] = (uint32_t(*)[GBK][AST])smu;
    uint32_t (*Bs)[GBK][BST] = (uint32_t(*)[GBK][BST])(smu + 2 * GBK * AST);

    const int tid  = threadIdx.x;
    const int wid  = tid >> 5, lane = tid & 31;
    const int gid  = lane >> 2, tig = lane & 3;
    const int wm   = (wid & 1) * 64;        // warp tile 64x32
    const int wn   = (wid >> 1) * 32;
    const int bm   = blockIdx.y * GBM;
    const int bn   = blockIdx.x * GBN;
    const int K4   = K >> 2, N4 = N >> 2;

    float acc[4][4][4];
    #pragma unroll
    for (int i = 0; i < 4; i++)
        #pragma unroll
        for (int j = 0; j < 4; j++)
            #pragma unroll
            for (int r = 0; r < 4; r++) acc[i][j][r] = 0.f;

    float4 ra[4], rb[4];

    // ---- global tile -> registers
    #define GLOAD(k0)                                                        \
        do {                                                                 \
            _Pragma("unroll")                                                \
            for (int t = 0; t < 4; t++) {                                    \
                int idx = tid + t * 256;                                     \
                int r = idx >> 3, c = idx & 7;                               \
                ra[t] = ((const float4*)A)[(size_t)(bm + r) * K4 + ((k0) >> 2) + c]; \
            }                                                                \
            _Pragma("unroll")                                                \
            for (int t = 0; t < 4; t++) {                                    \
                int idx = tid + t * 256;                                     \
                int r = idx >> 5, c = idx & 31;                              \
                rb[t] = ((const float4*)W)[(size_t)((k0) + r) * N4 + (bn >> 2) + c]; \
            }                                                                \
        } while (0)

    // ---- registers -> smem (with tf32 conversion)
    #define SSTORE(st)                                                       \
        do {                                                                 \
            _Pragma("unroll")                                                \
            for (int t = 0; t < 4; t++) {                                    \
                int idx = tid + t * 256;                                     \
                int r = idx >> 3, c = idx & 7;                               \
                float fv[4] = {ra[t].x, ra[t].y, ra[t].z, ra[t].w};          \
                _Pragma("unroll")                                            \
                for (int j = 0; j < 4; j++) {                                \
                    int k = c * 4 + j;                                       \
                    As[st][k][aswz(k, r)] = f2tf(fv[j]);                     \
                }                                                            \
            }                                                                \
            _Pragma("unroll")                                                \
            for (int t = 0; t < 4; t++) {                                    \
                int idx = tid + t * 256;                                     \
                int r = idx >> 5, c = idx & 31;                              \
                uint4 u;                                                     \
                u.x = f2tf(rb[t].x); u.y = f2tf(rb[t].y);                    \
                u.z = f2tf(rb[t].z); u.w = f2tf(rb[t].w);                    \
                *(uint4*)&Bs[st][r][c * 4] = u;                              \
            }                                                                \
        } while (0)

    GLOAD(0);
    SSTORE(0);
    __syncthreads();

    const int niter = K / GBK;
    int st = 0;
    for (int it = 0; it < niter; it++) {
        if (it + 1 < niter) GLOAD((it + 1) * GBK);

        #pragma unroll
        for (int ks = 0; ks < GBK; ks += 8) {
            uint32_t af[4][4], bf[4][2];
            #pragma unroll
            for (int mt = 0; mt < 4; mt++) {
                int m = wm + mt * 16;
                int k0 = ks + tig, k1 = ks + tig + 4;
                af[mt][0] = As[st][k0][aswz(k0, m + gid)];
                af[mt][1] = As[st][k0][aswz(k0, m + gid + 8)];
                af[mt][2] = As[st][k1][aswz(k1, m + gid)];
                af[mt][3] = As[st][k1][aswz(k1, m + gid + 8)];
            }
            #pragma unroll
            for (int nt = 0; nt < 4; nt++) {
                int n = wn + nt * 8;
                bf[nt][0] = Bs[st][ks + tig][n + gid];
                bf[nt][1] = Bs[st][ks + tig + 4][n + gid];
            }
            #pragma unroll
            for (int mt = 0; mt < 4; mt++)
                #pragma unroll
                for (int nt = 0; nt < 4; nt++)
                    mma8(acc[mt][nt], af[mt], bf[nt]);
        }

        if (it + 1 < niter) {
            __syncthreads();
            SSTORE(st ^ 1);
            __syncthreads();
            st ^= 1;
        }
    }

    // ---- epilogue: c0,c1 at (gid, 2*tig..+1); c2,c3 at (gid+8, ...)
    #pragma unroll
    for (int mt = 0; mt < 4; mt++) {
        #pragma unroll
        for (int half = 0; half < 2; half++) {
            int m = bm + wm + mt * 16 + gid + half * 8;
            #pragma unroll
            for (int nt = 0; nt < 4; nt++) {
                int n = bn + wn + nt * 8 + tig * 2;
                float2 v;
                v.x = acc[mt][nt][half * 2 + 0];
                v.y = acc[mt][nt][half * 2 + 1];
                if (EPI & 1) { v.x += bias[n]; v.y += bias[n + 1]; }
                if (EPI & 2) { v.x = fmaxf(v.x, 0.f); v.y = fmaxf(v.y, 0.f); }
                if (EPI & 4) {
                    float2 r = *(const float2*)&res[(size_t)m * N + n];
                    v.x += r.x; v.y += r.y;
                }
                *(float2*)&C[(size_t)m * N + n] = v;
            }
        }
    }
    #undef GLOAD
    #undef SSTORE
}

// ---------------- causal flash attention (64x64 tiles, HD=64) -------------
#define APAD 68
#define ATTN_SMEM ((4 * 64 * APAD + 192) * 4)

__global__ void __launch_bounds__(256) attn_kernel()
{
    int qi = blockIdx.x;
    int h  = blockIdx.y;
    int b  = blockIdx.z;
    extern __shared__ float sm[];
    float* Qs   = sm;
    float* Ks   = Qs + 64 * APAD;
    float* Vs   = Ks + 64 * APAD;
    float* Ss   = Vs + 64 * APAD;
    float* mrow = Ss + 64 * APAD;
    float* lrow = mrow + 64;
    float* arow = lrow + 64;

    int tid = threadIdx.x;
    int tx = tid & 15, ty = tid >> 4;

    for (int i = tid; i < 64 * 64; i += 256) {
        int r = i >> 6, e = i & 63;
        Qs[e * APAD + r] = g_q[(size_t)(b * T_ + (qi << 6) + r) * D_ + h * HD_ + e];
    }
    if (tid < 64) { mrow[tid] = -1e30f; lrow[tid] = 0.f; }

    float o[4][4];
    #pragma unroll
    for (int i = 0; i < 4; i++)
        #pragma unroll
        for (int j = 0; j < 4; j++) o[i][j] = 0.f;

    for (int kt = 0; kt <= qi; kt++) {
        __syncthreads();
        for (int i = tid; i < 64 * 64; i += 256) {
            int c = i >> 6, e = i & 63;
            size_t g = (size_t)(b * T_ + (kt << 6) + c) * D_ + h * HD_ + e;
            Ks[e * APAD + c] = g_k[g];
            Vs[c * APAD + e] = g_v[g];
        }
        __syncthreads();

        float s[4][4];
        #pragma unroll
        for (int i = 0; i < 4; i++)
            #pragma unroll
            for (int j = 0; j < 4; j++) s[i][j] = 0.f;
        #pragma unroll 8
        for (int e = 0; e < 64; e++) {
            float qv[4], kv[4];
            #pragma unroll
            for (int i = 0; i < 4; i++) qv[i] = Qs[e * APAD + ty * 4 + i];
            #pragma unroll
            for (int j = 0; j < 4; j++) kv[j] = Ks[e * APAD + tx * 4 + j];
            #pragma unroll
            for (int i = 0; i < 4; i++)
                #pragma unroll
                for (int j = 0; j < 4; j++)
                    s[i][j] += qv[i] * kv[j];
        }
        #pragma unroll
        for (int i = 0; i < 4; i++)
            #pragma unroll
            for (int j = 0; j < 4; j++) {
                float val = s[i][j] * 0.125f;
                if (kt == qi && (tx * 4 + j) > (ty * 4 + i)) val = -1e30f;
                Ss[(ty * 4 + i) * APAD + tx * 4 + j] = val;
            }
        __syncthreads();

        if (tid < 64) {
            int r = tid;
            float mo = mrow[r], mx = mo;
            #pragma unroll 8
            for (int c = 0; c < 64; c++) mx = fmaxf(mx, Ss[r * APAD + c]);
            float alpha = __expf(mo - mx);
            float sum = 0.f;
            #pragma unroll 8
            for (int c = 0; c < 64; c++) {
                float p = __expf(Ss[r * APAD + c] - mx);
                Ss[r * APAD + c] = p;
                sum += p;
            }
            lrow[r] = lrow[r] * alpha + sum;
            mrow[r] = mx;
            arow[r] = alpha;
        }
        __syncthreads();

        float al[4];
        #pragma unroll
        for (int i = 0; i < 4; i++) al[i] = arow[ty * 4 + i];
        #pragma unroll
        for (int i = 0; i < 4; i++)
            #pragma unroll
            for (int j = 0; j < 4; j++) o[i][j] *= al[i];
        #pragma unroll 8
        for (int c = 0; c < 64; c++) {
            float pv[4], vv[4];
            #pragma unroll
            for (int i = 0; i < 4; i++) pv[i] = Ss[(ty * 4 + i) * APAD + c];
            #pragma unroll
            for (int j = 0; j < 4; j++) vv[j] = Vs[c * APAD + tx * 4 + j];
            #pragma unroll
            for (int i = 0; i < 4; i++)
                #pragma unroll
                for (int j = 0; j < 4; j++)
                    o[i][j] += pv[i] * vv[j];
        }
    }

    #pragma unroll
    for (int i = 0; i < 4; i++) {
        float inv = 1.0f / lrow[ty * 4 + i];
        size_t base = (size_t)(b * T_ + (qi << 6) + ty * 4 + i) * D_ + h * HD_ + tx * 4;
        float4 v = make_float4(o[i][0] * inv, o[i][1] * inv, o[i][2] * inv, o[i][3] * inv);
        *(float4*)(g_ao + base) = v;
    }
}

// ---------------- host side ----------------------------------------------
static void launch_gemm(const float* A, const float* W, const float* bias,
                        const float* res, float* C, int M, int N, int K, int epi)
{
    dim3 grid(N / GBN, M / GBM), blk(256);
    switch (epi) {
        case 0: gemm_tc<0><<<grid, blk, GEMM_SMEM>>>(A, W, nullptr, nullptr, C, M, N, K); break;
        case 1: gemm_tc<1><<<grid, blk, GEMM_SMEM>>>(A, W, bias,    nullptr, C, M, N, K); break;
        case 3: gemm_tc<3><<<grid, blk, GEMM_SMEM>>>(A, W, bias,    nullptr, C, M, N, K); break;
        case 5: gemm_tc<5><<<grid, blk, GEMM_SMEM>>>(A, W, bias,    res,     C, M, N, K); break;
    }
}

extern "C" void kernel_launch(void* const* d_in, const int* in_sizes, int n_in,
                              void* d_out, int out_size)
{
    const int*   ctx  = (const int*)  d_in[0];
    const float* tok  = (const float*)d_in[1];
    const float* pos  = (const float*)d_in[2];
    const float* Wq   = (const float*)d_in[3];
    const float* Wk   = (const float*)d_in[4];
    const float* Wv   = (const float*)d_in[5];
    const float* Wo   = (const float*)d_in[6];
    const float* bo   = (const float*)d_in[7];
    const float* ln1s = (const float*)d_in[8];
    const float* ln1b = (const float*)d_in[9];
    const float* W1   = (const float*)d_in[10];
    const float* b1   = (const float*)d_in[11];
    const float* W2   = (const float*)d_in[12];
    const float* b2   = (const float*)d_in[13];
    const float* ln2s = (const float*)d_in[14];
    const float* ln2b = (const float*)d_in[15];
    const float* lnfs = (const float*)d_in[16];
    const float* lnfb = (const float*)d_in[17];
    const float* Wout = (const float*)d_in[18];
    const float* bout = (const float*)d_in[19];
    float* out = (float*)d_out;

    float *x, *h, *q, *k, *v, *ao, *ff;
    cudaGetSymbolAddress((void**)&x,  g_x);
    cudaGetSymbolAddress((void**)&h,  g_h);
    cudaGetSymbolAddress((void**)&q,  g_q);
    cudaGetSymbolAddress((void**)&k,  g_k);
    cudaGetSymbolAddress((void**)&v,  g_v);
    cudaGetSymbolAddress((void**)&ao, g_ao);
    cudaGetSymbolAddress((void**)&ff, g_ff);

    cudaFuncSetAttribute(attn_kernel,
                         cudaFuncAttributeMaxDynamicSharedMemorySize, ATTN_SMEM);
    cudaFuncSetAttribute(gemm_tc<0>, cudaFuncAttributeMaxDynamicSharedMemorySize, GEMM_SMEM);
    cudaFuncSetAttribute(gemm_tc<1>, cudaFuncAttributeMaxDynamicSharedMemorySize, GEMM_SMEM);
    cudaFuncSetAttribute(gemm_tc<3>, cudaFuncAttributeMaxDynamicSharedMemorySize, GEMM_SMEM);
    cudaFuncSetAttribute(gemm_tc<5>, cudaFuncAttributeMaxDynamicSharedMemorySize, GEMM_SMEM);

    embed_kernel<<<BT * D_ / 1024, 256>>>(ctx, (const float4*)tok, (const float4*)pos);

    for (int l = 0; l < L_; l++) {
        ln_kernel<<<BT, 256>>>(x, ln1s + (size_t)l * D_, ln1b + (size_t)l * D_, h);
        launch_gemm(h, Wq + (size_t)l * D_ * D_, nullptr, nullptr, q, BT, D_, D_, 0);
        launch_gemm(h, Wk + (size_t)l * D_ * D_, nullptr, nullptr, k, BT, D_, D_, 0);
        launch_gemm(h, Wv + (size_t)l * D_ * D_, nullptr, nullptr, v, BT, D_, D_, 0);
        attn_kernel<<<dim3(T_ / 64, H_, Bz), 256, ATTN_SMEM>>>();
        launch_gemm(ao, Wo + (size_t)l * D_ * D_, bo + (size_t)l * D_, x, x, BT, D_, D_, 5);
        ln_kernel<<<BT, 256>>>(x, ln2s + (size_t)l * D_, ln2b + (size_t)l * D_, h);
        launch_gemm(h, W1 + (size_t)l * D_ * FF_, b1 + (size_t)l * FF_, nullptr, ff, BT, FF_, D_, 3);
        launch_gemm(ff, W2 + (size_t)l * FF_ * D_, b2 + (size_t)l * D_, x, x, BT, D_, FF_, 5);
    }
    ln_kernel<<<BT, 256>>>(x, lnfs, lnfb, h);
    launch_gemm(h, Wout, bout, nullptr, out, BT, V_, D_, 1);
}

// round 6
// speedup vs baseline: 2.3313x; 1.1888x over previous
#include <cuda_runtime.h>
#include <cstdint>

#define Bz  2
#define T_  2048
#define BT  4096
#define D_  1024
#define H_  16
#define HD_ 64
#define L_  4
#define V_  32000
#define FF_ 4096

// ---------------- scratch (static device memory; no allocations) ----------
__device__ float g_x [BT * D_];
__device__ float g_h [BT * D_];
__device__ float g_q [BT * D_];
__device__ float g_k [BT * D_];
__device__ float g_v [BT * D_];
__device__ float g_ao[BT * D_];
__device__ float g_ff[BT * FF_];

// ---------------- embedding ----------------------------------------------
__global__ void embed_kernel(const int* __restrict__ ctx,
                             const float4* __restrict__ tok,
                             const float4* __restrict__ pos)
{
    int i   = blockIdx.x * 256 + threadIdx.x;
    int row = i / (D_ / 4);
    int c   = i - row * (D_ / 4);
    int t   = row & (T_ - 1);
    float4 a = tok[(size_t)ctx[row] * (D_ / 4) + c];
    float4 b = pos[(size_t)t * (D_ / 4) + c];
    ((float4*)g_x)[i] = make_float4(a.x + b.x, a.y + b.y, a.z + b.z, a.w + b.w);
}

// ---------------- layernorm ----------------------------------------------
__global__ void ln_kernel(const float* __restrict__ in,
                          const float* __restrict__ gamma,
                          const float* __restrict__ beta,
                          float* __restrict__ out)
{
    int row = blockIdx.x;
    const float4* r4 = (const float4*)(in + (size_t)row * D_);
    float4 v = r4[threadIdx.x];
    float s  = v.x + v.y + v.z + v.w;
    float ss = v.x * v.x + v.y * v.y + v.z * v.z + v.w * v.w;
    #pragma unroll
    for (int o = 16; o > 0; o >>= 1) {
        s  += __shfl_xor_sync(0xffffffffu, s,  o);
        ss += __shfl_xor_sync(0xffffffffu, ss, o);
    }
    __shared__ float shs[8], shss[8];
    int w = threadIdx.x >> 5, lane = threadIdx.x & 31;
    if (lane == 0) { shs[w] = s; shss[w] = ss; }
    __syncthreads();
    float ts = 0.f, tss = 0.f;
    #pragma unroll
    for (int i = 0; i < 8; i++) { ts += shs[i]; tss += shss[i]; }
    float mean = ts * (1.0f / D_);
    float var  = tss * (1.0f / D_) - mean * mean;
    float inv  = rsqrtf(var + 1e-5f);
    float4 g  = ((const float4*)gamma)[threadIdx.x];
    float4 bb = ((const float4*)beta)[threadIdx.x];
    float4 o;
    o.x = (v.x - mean) * inv * g.x + bb.x;
    o.y = (v.y - mean) * inv * g.y + bb.y;
    o.z = (v.z - mean) * inv * g.z + bb.z;
    o.w = (v.w - mean) * inv * g.w + bb.w;
    ((float4*)(out + (size_t)row * D_))[threadIdx.x] = o;
}

// ---------------- TF32 tensor-core GEMM ------------------------------------
// C = epi(A[M,K] @ W[K,N]); EPI bit0:+bias  bit1:relu  bit2:+res
#define GBM 128
#define GBN 128
#define GBK 32
#define AFS 4096               // A frag floats per stage: 2*4*4*32*4
#define BROW 136               // Bs row stride (floats)
#define BFS (GBK * BROW)       // 4352
#define GEMM_SMEM ((2 * AFS + 2 * BFS) * 4)

__device__ __forceinline__ uint32_t f2tf(float f)
{
    uint32_t r;
    asm("cvt.rna.tf32.f32 %0, %1;" : "=r"(r) : "f"(f));
    return r;
}

__device__ __forceinline__ void mma8(float* c, const uint32_t* a, const uint32_t* b)
{
    asm volatile(
        "mma.sync.aligned.m16n8k8.row.col.f32.tf32.tf32.f32 "
        "{%0,%1,%2,%3}, {%4,%5,%6,%7}, {%8,%9}, {%0,%1,%2,%3};"
        : "+f"(c[0]), "+f"(c[1]), "+f"(c[2]), "+f"(c[3])
        : "r"(a[0]), "r"(a[1]), "r"(a[2]), "r"(a[3]), "r"(b[0]), "r"(b[1]));
}

template <int EPI>
__device__ __forceinline__ void
gemm_core(const float* __restrict__ A, const float* __restrict__ W,
          const float* __restrict__ bias, const float* __restrict__ res,
          float* __restrict__ C, int M, int N, int K)
{
    extern __shared__ uint32_t smu[];
    uint32_t* AF = smu;                                   // [2][AFS]
    uint32_t (*Bs)[GBK][BROW] = (uint32_t(*)[GBK][BROW])(smu + 2 * AFS);

    const int tid  = threadIdx.x;
    const int wid  = tid >> 5, lane = tid & 31;
    const int gid  = lane >> 2, tig = lane & 3;
    const int wmi  = wid & 1;               // warp tile 64x32
    const int wn   = (wid >> 1) * 32;
    const int bm   = blockIdx.y * GBM;
    const int bn   = blockIdx.x * GBN;
    const int K4   = K >> 2, N4 = N >> 2;

    float acc[4][4][4];
    #pragma unroll
    for (int i = 0; i < 4; i++)
        #pragma unroll
        for (int j = 0; j < 4; j++)
            #pragma unroll
            for (int r = 0; r < 4; r++) acc[i][j][r] = 0.f;

    float4 ra[4], rb[4];

    #define GLOAD(k0)                                                        \
        do {                                                                 \
            _Pragma("unroll")                                                \
            for (int t = 0; t < 4; t++) {                                    \
                int idx = tid + t * 256;                                     \
                int r = idx >> 3, c = idx & 7;                               \
                ra[t] = ((const float4*)A)[(size_t)(bm + r) * K4 + ((k0) >> 2) + c]; \
            }                                                                \
            _Pragma("unroll")                                                \
            for (int t = 0; t < 4; t++) {                                    \
                int idx = tid + t * 256;                                     \
                int r = idx >> 5, c = idx & 31;                              \
                rb[t] = ((const float4*)W)[(size_t)((k0) + r) * N4 + (bn >> 2) + c]; \
            }                                                                \
        } while (0)

    // A -> fragment-major layout AF[wmi][ks][mt][lane^ks][reg]
    #define SSTORE(st)                                                       \
        do {                                                                 \
            _Pragma("unroll")                                                \
            for (int t = 0; t < 4; t++) {                                    \
                int idx = tid + t * 256;                                     \
                int r = idx >> 3, c = idx & 7;                               \
                int awmi = r >> 6, rr = r & 63;                              \
                int mt = rr >> 4, rh = (rr >> 3) & 1, agid = rr & 7;         \
                int ks = c >> 1, reg = rh + 2 * (c & 1);                     \
                uint32_t* p = AF + (st) * AFS +                              \
                              (((awmi * 4 + ks) * 4 + mt) << 7) + reg;       \
                float fv[4] = {ra[t].x, ra[t].y, ra[t].z, ra[t].w};          \
                _Pragma("unroll")                                            \
                for (int j = 0; j < 4; j++)                                  \
                    p[(((agid * 4 + j) ^ ks) << 2)] = f2tf(fv[j]);           \
            }                                                                \
            _Pragma("unroll")                                                \
            for (int t = 0; t < 4; t++) {                                    \
                int idx = tid + t * 256;                                     \
                int r = idx >> 5, c = idx & 31;                              \
                uint4 u;                                                     \
                u.x = f2tf(rb[t].x); u.y = f2tf(rb[t].y);                    \
                u.z = f2tf(rb[t].z); u.w = f2tf(rb[t].w);                    \
                *(uint4*)&Bs[st][r][c * 4] = u;                              \
            }                                                                \
        } while (0)

    GLOAD(0);
    SSTORE(0);
    __syncthreads();

    const int niter = K / GBK;
    int st = 0;
    for (int it = 0; it < niter; it++) {
        if (it + 1 < niter) GLOAD((it + 1) * GBK);

        const uint32_t* Awarp = AF + st * AFS + (wmi << 11);
        #pragma unroll
        for (int ks = 0; ks < 4; ks++) {
            uint32_t af[4][4], bf[4][2];
            int ls = ((lane ^ ks) << 2);
            #pragma unroll
            for (int mt = 0; mt < 4; mt++) {
                uint4 a4 = *(const uint4*)(Awarp + ((ks * 4 + mt) << 7) + ls);
                af[mt][0] = a4.x; af[mt][1] = a4.y;
                af[mt][2] = a4.z; af[mt][3] = a4.w;
            }
            #pragma unroll
            for (int nt = 0; nt < 4; nt++) {
                bf[nt][0] = Bs[st][ks * 8 + tig][wn + nt * 8 + gid];
                bf[nt][1] = Bs[st][ks * 8 + tig + 4][wn + nt * 8 + gid];
            }
            #pragma unroll
            for (int mt = 0; mt < 4; mt++)
                #pragma unroll
                for (int nt = 0; nt < 4; nt++)
                    mma8(acc[mt][nt], af[mt], bf[nt]);
        }

        if (it + 1 < niter) {
            SSTORE(st ^ 1);          // writes non-live stage; no pre-sync needed
            __syncthreads();
            st ^= 1;
        }
    }

    // ---- epilogue
    const int wm = wmi * 64;
    #pragma unroll
    for (int mt = 0; mt < 4; mt++) {
        #pragma unroll
        for (int half = 0; half < 2; half++) {
            int m = bm + wm + mt * 16 + gid + half * 8;
            #pragma unroll
            for (int nt = 0; nt < 4; nt++) {
                int n = bn + wn + nt * 8 + tig * 2;
                float2 v;
                v.x = acc[mt][nt][half * 2 + 0];
                v.y = acc[mt][nt][half * 2 + 1];
                if (EPI & 1) { v.x += bias[n]; v.y += bias[n + 1]; }
                if (EPI & 2) { v.x = fmaxf(v.x, 0.f); v.y = fmaxf(v.y, 0.f); }
                if (EPI & 4) {
                    float2 r = *(const float2*)&res[(size_t)m * N + n];
                    v.x += r.x; v.y += r.y;
                }
                *(float2*)&C[(size_t)m * N + n] = v;
            }
        }
    }
    #undef GLOAD
    #undef SSTORE
}

template <int EPI>
__global__ void __launch_bounds__(256)
gemm_tc(const float* __restrict__ A, const float* __restrict__ W,
        const float* __restrict__ bias, const float* __restrict__ res,
        float* __restrict__ C, int M, int N, int K)
{
    gemm_core<EPI>(A, W, bias, res, C, M, N, K);
}

struct QKVArgs { const float *w0, *w1, *w2; float *c0, *c1, *c2; };

__global__ void __launch_bounds__(256)
gemm_qkv(const float* __restrict__ A, QKVArgs p, int M, int N, int K)
{
    const float* W = (blockIdx.z == 0) ? p.w0 : (blockIdx.z == 1) ? p.w1 : p.w2;
    float*       C = (blockIdx.z == 0) ? p.c0 : (blockIdx.z == 1) ? p.c1 : p.c2;
    gemm_core<0>(A, W, nullptr, nullptr, C, M, N, K);
}

// ---------------- causal flash attention (64x64 tiles, HD=64) -------------
#define APAD 68
#define ATTN_SMEM ((4 * 64 * APAD + 192) * 4)

__global__ void __launch_bounds__(256) attn_kernel()
{
    int qi = blockIdx.x;
    int h  = blockIdx.y;
    int b  = blockIdx.z;
    extern __shared__ float sm[];
    float* Qs   = sm;
    float* Ks   = Qs + 64 * APAD;
    float* Vs   = Ks + 64 * APAD;
    float* Ss   = Vs + 64 * APAD;
    float* mrow = Ss + 64 * APAD;
    float* lrow = mrow + 64;
    float* arow = lrow + 64;

    int tid = threadIdx.x;
    int tx = tid & 15, ty = tid >> 4;

    for (int i = tid; i < 64 * 64; i += 256) {
        int r = i >> 6, e = i & 63;
        Qs[e * APAD + r] = g_q[(size_t)(b * T_ + (qi << 6) + r) * D_ + h * HD_ + e];
    }
    if (tid < 64) { mrow[tid] = -1e30f; lrow[tid] = 0.f; }

    float o[4][4];
    #pragma unroll
    for (int i = 0; i < 4; i++)
        #pragma unroll
        for (int j = 0; j < 4; j++) o[i][j] = 0.f;

    for (int kt = 0; kt <= qi; kt++) {
        __syncthreads();
        for (int i = tid; i < 64 * 64; i += 256) {
            int c = i >> 6, e = i & 63;
            size_t g = (size_t)(b * T_ + (kt << 6) + c) * D_ + h * HD_ + e;
            Ks[e * APAD + c] = g_k[g];
            Vs[c * APAD + e] = g_v[g];
        }
        __syncthreads();

        float s[4][4];
        #pragma unroll
        for (int i = 0; i < 4; i++)
            #pragma unroll
            for (int j = 0; j < 4; j++) s[i][j] = 0.f;
        #pragma unroll 8
        for (int e = 0; e < 64; e++) {
            float qv[4], kv[4];
            #pragma unroll
            for (int i = 0; i < 4; i++) qv[i] = Qs[e * APAD + ty * 4 + i];
            #pragma unroll
            for (int j = 0; j < 4; j++) kv[j] = Ks[e * APAD + tx * 4 + j];
            #pragma unroll
            for (int i = 0; i < 4; i++)
                #pragma unroll
                for (int j = 0; j < 4; j++)
                    s[i][j] += qv[i] * kv[j];
        }
        #pragma unroll
        for (int i = 0; i < 4; i++)
            #pragma unroll
            for (int j = 0; j < 4; j++) {
                float val = s[i][j] * 0.125f;
                if (kt == qi && (tx * 4 + j) > (ty * 4 + i)) val = -1e30f;
                Ss[(ty * 4 + i) * APAD + tx * 4 + j] = val;
            }
        __syncthreads();

        if (tid < 64) {
            int r = tid;
            float mo = mrow[r], mx = mo;
            #pragma unroll 8
            for (int c = 0; c < 64; c++) mx = fmaxf(mx, Ss[r * APAD + c]);
            float alpha = __expf(mo - mx);
            float sum = 0.f;
            #pragma unroll 8
            for (int c = 0; c < 64; c++) {
                float p = __expf(Ss[r * APAD + c] - mx);
                Ss[r * APAD + c] = p;
                sum += p;
            }
            lrow[r] = lrow[r] * alpha + sum;
            mrow[r] = mx;
            arow[r] = alpha;
        }
        __syncthreads();

        float al[4];
        #pragma unroll
        for (int i = 0; i < 4; i++) al[i] = arow[ty * 4 + i];
        #pragma unroll
        for (int i = 0; i < 4; i++)
            #pragma unroll
            for (int j = 0; j < 4; j++) o[i][j] *= al[i];
        #pragma unroll 8
        for (int c = 0; c < 64; c++) {
            float pv[4], vv[4];
            #pragma unroll
            for (int i = 0; i < 4; i++) pv[i] = Ss[(ty * 4 + i) * APAD + c];
            #pragma unroll
            for (int j = 0; j < 4; j++) vv[j] = Vs[c * APAD + tx * 4 + j];
            #pragma unroll
            for (int i = 0; i < 4; i++)
                #pragma unroll
                for (int j = 0; j < 4; j++)
                    o[i][j] += pv[i] * vv[j];
        }
    }

    #pragma unroll
    for (int i = 0; i < 4; i++) {
        float inv = 1.0f / lrow[ty * 4 + i];
        size_t base = (size_t)(b * T_ + (qi << 6) + ty * 4 + i) * D_ + h * HD_ + tx * 4;
        float4 v = make_float4(o[i][0] * inv, o[i][1] * inv, o[i][2] * inv, o[i][3] * inv);
        *(float4*)(g_ao + base) = v;
    }
}

// ---------------- host side ----------------------------------------------
static void launch_gemm(const float* A, const float* W, const float* bias,
                        const float* res, float* C, int M, int N, int K, int epi)
{
    dim3 grid(N / GBN, M / GBM), blk(256);
    switch (epi) {
        case 0: gemm_tc<0><<<grid, blk, GEMM_SMEM>>>(A, W, nullptr, nullptr, C, M, N, K); break;
        case 1: gemm_tc<1><<<grid, blk, GEMM_SMEM>>>(A, W, bias,    nullptr, C, M, N, K); break;
        case 3: gemm_tc<3><<<grid, blk, GEMM_SMEM>>>(A, W, bias,    nullptr, C, M, N, K); break;
        case 5: gemm_tc<5><<<grid, blk, GEMM_SMEM>>>(A, W, bias,    res,     C, M, N, K); break;
    }
}

extern "C" void kernel_launch(void* const* d_in, const int* in_sizes, int n_in,
                              void* d_out, int out_size)
{
    const int*   ctx  = (const int*)  d_in[0];
    const float* tok  = (const float*)d_in[1];
    const float* pos  = (const float*)d_in[2];
    const float* Wq   = (const float*)d_in[3];
    const float* Wk   = (const float*)d_in[4];
    const float* Wv   = (const float*)d_in[5];
    const float* Wo   = (const float*)d_in[6];
    const float* bo   = (const float*)d_in[7];
    const float* ln1s = (const float*)d_in[8];
    const float* ln1b = (const float*)d_in[9];
    const float* W1   = (const float*)d_in[10];
    const float* b1   = (const float*)d_in[11];
    const float* W2   = (const float*)d_in[12];
    const float* b2   = (const float*)d_in[13];
    const float* ln2s = (const float*)d_in[14];
    const float* ln2b = (const float*)d_in[15];
    const float* lnfs = (const float*)d_in[16];
    const float* lnfb = (const float*)d_in[17];
    const float* Wout = (const float*)d_in[18];
    const float* bout = (const float*)d_in[19];
    float* out = (float*)d_out;

    float *x, *h, *q, *k, *v, *ao, *ff;
    cudaGetSymbolAddress((void**)&x,  g_x);
    cudaGetSymbolAddress((void**)&h,  g_h);
    cudaGetSymbolAddress((void**)&q,  g_q);
    cudaGetSymbolAddress((void**)&k,  g_k);
    cudaGetSymbolAddress((void**)&v,  g_v);
    cudaGetSymbolAddress((void**)&ao, g_ao);
    cudaGetSymbolAddress((void**)&ff, g_ff);

    cudaFuncSetAttribute(attn_kernel,
                         cudaFuncAttributeMaxDynamicSharedMemorySize, ATTN_SMEM);
    cudaFuncSetAttribute(gemm_tc<0>, cudaFuncAttributeMaxDynamicSharedMemorySize, GEMM_SMEM);
    cudaFuncSetAttribute(gemm_tc<1>, cudaFuncAttributeMaxDynamicSharedMemorySize, GEMM_SMEM);
    cudaFuncSetAttribute(gemm_tc<3>, cudaFuncAttributeMaxDynamicSharedMemorySize, GEMM_SMEM);
    cudaFuncSetAttribute(gemm_tc<5>, cudaFuncAttributeMaxDynamicSharedMemorySize, GEMM_SMEM);
    cudaFuncSetAttribute(gemm_qkv,   cudaFuncAttributeMaxDynamicSharedMemorySize, GEMM_SMEM);

    embed_kernel<<<BT * D_ / 1024, 256>>>(ctx, (const float4*)tok, (const float4*)pos);

    for (int l = 0; l < L_; l++) {
        ln_kernel<<<BT, 256>>>(x, ln1s + (size_t)l * D_, ln1b + (size_t)l * D_, h);
        QKVArgs p { Wq + (size_t)l * D_ * D_, Wk + (size_t)l * D_ * D_,
                    Wv + (size_t)l * D_ * D_, q, k, v };
        gemm_qkv<<<dim3(D_ / GBN, BT / GBM, 3), 256, GEMM_SMEM>>>(h, p, BT, D_, D_);
        attn_kernel<<<dim3(T_ / 64, H_, Bz), 256, ATTN_SMEM>>>();
        launch_gemm(ao, Wo + (size_t)l * D_ * D_, bo + (size_t)l * D_, x, x, BT, D_, D_, 5);
        ln_kernel<<<BT, 256>>>(x, ln2s + (size_t)l * D_, ln2b + (size_t)l * D_, h);
        launch_gemm(h, W1 + (size_t)l * D_ * FF_, b1 + (size_t)l * FF_, nullptr, ff, BT, FF_, D_, 3);
        launch_gemm(ff, W2 + (size_t)l * FF_ * D_, b2 + (size_t)l * D_, x, x, BT, D_, FF_, 5);
    }
    ln_kernel<<<BT, 256>>>(x, lnfs, lnfb, h);
    launch_gemm(h, Wout, bout, nullptr, out, BT, V_, D_, 1);
}

// round 8
// speedup vs baseline: 2.6860x; 1.1521x over previous
#include <cuda_runtime.h>
#include <cstdint>

#define Bz  2
#define T_  2048
#define BT  4096
#define D_  1024
#define H_  16
#define HD_ 64
#define L_  4
#define V_  32000
#define FF_ 4096

// ---------------- scratch (static device memory; no allocations) ----------
__device__ float g_x [BT * D_];
__device__ float g_h [BT * D_];
__device__ float g_q [BT * D_];
__device__ float g_k [BT * D_];
__device__ float g_v [BT * D_];
__device__ float g_ao[BT * D_];
__device__ float g_ff[BT * FF_];

// ---------------- embedding ----------------------------------------------
__global__ void embed_kernel(const int* __restrict__ ctx,
                             const float4* __restrict__ tok,
                             const float4* __restrict__ pos)
{
    int i   = blockIdx.x * 256 + threadIdx.x;
    int row = i / (D_ / 4);
    int c   = i - row * (D_ / 4);
    int t   = row & (T_ - 1);
    float4 a = tok[(size_t)ctx[row] * (D_ / 4) + c];
    float4 b = pos[(size_t)t * (D_ / 4) + c];
    ((float4*)g_x)[i] = make_float4(a.x + b.x, a.y + b.y, a.z + b.z, a.w + b.w);
}

// ---------------- layernorm ----------------------------------------------
__global__ void ln_kernel(const float* __restrict__ in,
                          const float* __restrict__ gamma,
                          const float* __restrict__ beta,
                          float* __restrict__ out)
{
    int row = blockIdx.x;
    const float4* r4 = (const float4*)(in + (size_t)row * D_);
    float4 v = r4[threadIdx.x];
    float s  = v.x + v.y + v.z + v.w;
    float ss = v.x * v.x + v.y * v.y + v.z * v.z + v.w * v.w;
    #pragma unroll
    for (int o = 16; o > 0; o >>= 1) {
        s  += __shfl_xor_sync(0xffffffffu, s,  o);
        ss += __shfl_xor_sync(0xffffffffu, ss, o);
    }
    __shared__ float shs[8], shss[8];
    int w = threadIdx.x >> 5, lane = threadIdx.x & 31;
    if (lane == 0) { shs[w] = s; shss[w] = ss; }
    __syncthreads();
    float ts = 0.f, tss = 0.f;
    #pragma unroll
    for (int i = 0; i < 8; i++) { ts += shs[i]; tss += shss[i]; }
    float mean = ts * (1.0f / D_);
    float var  = tss * (1.0f / D_) - mean * mean;
    float inv  = rsqrtf(var + 1e-5f);
    float4 g  = ((const float4*)gamma)[threadIdx.x];
    float4 bb = ((const float4*)beta)[threadIdx.x];
    float4 o;
    o.x = (v.x - mean) * inv * g.x + bb.x;
    o.y = (v.y - mean) * inv * g.y + bb.y;
    o.z = (v.z - mean) * inv * g.z + bb.z;
    o.w = (v.w - mean) * inv * g.w + bb.w;
    ((float4*)(out + (size_t)row * D_))[threadIdx.x] = o;
}

// ---------------- TF32 helpers --------------------------------------------
__device__ __forceinline__ uint32_t f2tf(float f)
{
    uint32_t r;
    asm("cvt.rna.tf32.f32 %0, %1;" : "=r"(r) : "f"(f));
    return r;
}

__device__ __forceinline__ void mma8(float* c, const uint32_t* a, const uint32_t* b)
{
    asm volatile(
        "mma.sync.aligned.m16n8k8.row.col.f32.tf32.tf32.f32 "
        "{%0,%1,%2,%3}, {%4,%5,%6,%7}, {%8,%9}, {%0,%1,%2,%3};"
        : "+f"(c[0]), "+f"(c[1]), "+f"(c[2]), "+f"(c[3])
        : "r"(a[0]), "r"(a[1]), "r"(a[2]), "r"(a[3]), "r"(b[0]), "r"(b[1]));
}

// ---------------- TF32 tensor-core GEMM ------------------------------------
#define GBM 128
#define GBN 128
#define GBK 32
#define AFS 4096
#define BROW 136
#define BFS (GBK * BROW)
#define GEMM_SMEM ((2 * AFS + 2 * BFS) * 4)

template <int EPI>
__device__ __forceinline__ void
gemm_core(const float* __restrict__ A, const float* __restrict__ W,
          const float* __restrict__ bias, const float* __restrict__ res,
          float* __restrict__ C, int M, int N, int K)
{
    extern __shared__ uint32_t smu[];
    uint32_t* AF = smu;
    uint32_t (*Bs)[GBK][BROW] = (uint32_t(*)[GBK][BROW])(smu + 2 * AFS);

    const int tid  = threadIdx.x;
    const int wid  = tid >> 5, lane = tid & 31;
    const int gid  = lane >> 2, tig = lane & 3;
    const int wmi  = wid & 1;
    const int wn   = (wid >> 1) * 32;
    const int bm   = blockIdx.y * GBM;
    const int bn   = blockIdx.x * GBN;
    const int K4   = K >> 2, N4 = N >> 2;

    float acc[4][4][4];
    #pragma unroll
    for (int i = 0; i < 4; i++)
        #pragma unroll
        for (int j = 0; j < 4; j++)
            #pragma unroll
            for (int r = 0; r < 4; r++) acc[i][j][r] = 0.f;

    float4 ra[4], rb[4];

    #define GLOAD(k0)                                                        \
        do {                                                                 \
            _Pragma("unroll")                                                \
            for (int t = 0; t < 4; t++) {                                    \
                int idx = tid + t * 256;                                     \
                int r = idx >> 3, c = idx & 7;                               \
                ra[t] = ((const float4*)A)[(size_t)(bm + r) * K4 + ((k0) >> 2) + c]; \
            }                                                                \
            _Pragma("unroll")                                                \
            for (int t = 0; t < 4; t++) {                                    \
                int idx = tid + t * 256;                                     \
                int r = idx >> 5, c = idx & 31;                              \
                rb[t] = ((const float4*)W)[(size_t)((k0) + r) * N4 + (bn >> 2) + c]; \
            }                                                                \
        } while (0)

    #define SSTORE(st)                                                       \
        do {                                                                 \
            _Pragma("unroll")                                                \
            for (int t = 0; t < 4; t++) {                                    \
                int idx = tid + t * 256;                                     \
                int r = idx >> 3, c = idx & 7;                               \
                int awmi = r >> 6, rr = r & 63;                              \
                int mt = rr >> 4, rh = (rr >> 3) & 1, agid = rr & 7;         \
                int ks = c >> 1, reg = rh + 2 * (c & 1);                     \
                uint32_t* p = AF + (st) * AFS +                              \
                              (((awmi * 4 + ks) * 4 + mt) << 7) + reg;       \
                float fv[4] = {ra[t].x, ra[t].y, ra[t].z, ra[t].w};          \
                _Pragma("unroll")                                            \
                for (int j = 0; j < 4; j++)                                  \
                    p[(((agid * 4 + j) ^ ks) << 2)] = f2tf(fv[j]);           \
            }                                                                \
            _Pragma("unroll")                                                \
            for (int t = 0; t < 4; t++) {                                    \
                int idx = tid + t * 256;                                     \
                int r = idx >> 5, c = idx & 31;                              \
                uint4 u;                                                     \
                u.x = f2tf(rb[t].x); u.y = f2tf(rb[t].y);                    \
                u.z = f2tf(rb[t].z); u.w = f2tf(rb[t].w);                    \
                *(uint4*)&Bs[st][r][c * 4] = u;                              \
            }                                                                \
        } while (0)

    GLOAD(0);
    SSTORE(0);
    __syncthreads();

    const int niter = K / GBK;
    int st = 0;
    for (int it = 0; it < niter; it++) {
        if (it + 1 < niter) GLOAD((it + 1) * GBK);

        const uint32_t* Awarp = AF + st * AFS + (wmi << 11);
        #pragma unroll
        for (int ks = 0; ks < 4; ks++) {
            uint32_t af[4][4], bf[4][2];
            int ls = ((lane ^ ks) << 2);
            #pragma unroll
            for (int mt = 0; mt < 4; mt++) {
                uint4 a4 = *(const uint4*)(Awarp + ((ks * 4 + mt) << 7) + ls);
                af[mt][0] = a4.x; af[mt][1] = a4.y;
                af[mt][2] = a4.z; af[mt][3] = a4.w;
            }
            #pragma unroll
            for (int nt = 0; nt < 4; nt++) {
                bf[nt][0] = Bs[st][ks * 8 + tig][wn + nt * 8 + gid];
                bf[nt][1] = Bs[st][ks * 8 + tig + 4][wn + nt * 8 + gid];
            }
            #pragma unroll
            for (int mt = 0; mt < 4; mt++)
                #pragma unroll
                for (int nt = 0; nt < 4; nt++)
                    mma8(acc[mt][nt], af[mt], bf[nt]);
        }

        if (it + 1 < niter) {
            SSTORE(st ^ 1);
            __syncthreads();
            st ^= 1;
        }
    }

    const int wm = wmi * 64;
    #pragma unroll
    for (int mt = 0; mt < 4; mt++) {
        #pragma unroll
        for (int half = 0; half < 2; half++) {
            int m = bm + wm + mt * 16 + gid + half * 8;
            #pragma unroll
            for (int nt = 0; nt < 4; nt++) {
                int n = bn + wn + nt * 8 + tig * 2;
                float2 v;
                v.x = acc[mt][nt][half * 2 + 0];
                v.y = acc[mt][nt][half * 2 + 1];
                if (EPI & 1) { v.x += bias[n]; v.y += bias[n + 1]; }
                if (EPI & 2) { v.x = fmaxf(v.x, 0.f); v.y = fmaxf(v.y, 0.f); }
                if (EPI & 4) {
                    float2 r = *(const float2*)&res[(size_t)m * N + n];
                    v.x += r.x; v.y += r.y;
                }
                *(float2*)&C[(size_t)m * N + n] = v;
            }
        }
    }
    #undef GLOAD
    #undef SSTORE
}

template <int EPI>
__global__ void __launch_bounds__(256)
gemm_tc(const float* __restrict__ A, const float* __restrict__ W,
        const float* __restrict__ bias, const float* __restrict__ res,
        float* __restrict__ C, int M, int N, int K)
{
    gemm_core<EPI>(A, W, bias, res, C, M, N, K);
}

struct QKVArgs { const float *w0, *w1, *w2; float *c0, *c1, *c2; };

__global__ void __launch_bounds__(256)
gemm_qkv(const float* __restrict__ A, QKVArgs p, int M, int N, int K)
{
    const float* W = (blockIdx.z == 0) ? p.w0 : (blockIdx.z == 1) ? p.w1 : p.w2;
    float*       C = (blockIdx.z == 0) ? p.c0 : (blockIdx.z == 1) ? p.c1 : p.c2;
    gemm_core<0>(A, W, nullptr, nullptr, C, M, N, K);
}

// ---------------- TF32 tensor-core causal flash attention ------------------
// 64x64 tiles, HD=64. 8 warps: 4(m) x 2(n). S in split-tf32 (3 mma), PV plain.
#define AQS 68                       // padded row stride (floats)
#define ATILE (64 * AQS)             // 4352
#define ATTN_SMEM ((6 * ATILE + 3 * 64 + 2 * 256) * 4)

__global__ void __launch_bounds__(256) attn_tc_kernel()
{
    int qi = blockIdx.x, h = blockIdx.y, b = blockIdx.z;
    extern __shared__ float sma[];
    uint32_t* QH = (uint32_t*)sma;                 // [64][AQS] tf32 hi
    uint32_t* QL = QH + ATILE;                     // tf32 lo
    uint32_t* KH = QH + 2 * ATILE;
    uint32_t* KL = QH + 3 * ATILE;
    uint32_t* VT = QH + 4 * ATILE;                 // V^T [e][c]
    float*    SS = sma + 5 * ATILE;                // [64][AQS] scores / probs
    float*    MR = sma + 6 * ATILE;                // 64
    float*    LR = MR + 64;
    float*    AR = MR + 128;
    float*    PM = MR + 192;                       // 256 partial max
    float*    PS = PM + 256;                       // 256 partial sum

    const int tid = threadIdx.x;
    const int lane = tid & 31, wid = tid >> 5;
    const int gid = lane >> 2, tig = lane & 3;
    const int r0  = (wid & 3) * 16;                // warp m-rows
    const int n0s = (wid >> 2) * 32;               // warp n-cols

    // load Q (hi/lo split)
    for (int i = tid; i < 64 * 64; i += 256) {
        int r = i >> 6, e = i & 63;
        float f = g_q[(size_t)(b * T_ + (qi << 6) + r) * D_ + h * HD_ + e];
        uint32_t hi = f2tf(f);
        QH[r * AQS + e] = hi;
        QL[r * AQS + e] = f2tf(f - __uint_as_float(hi));
    }
    if (tid < 64) { MR[tid] = -1e30f; LR[tid] = 0.f; }

    float oacc[4][4];
    #pragma unroll
    for (int i = 0; i < 4; i++)
        #pragma unroll
        for (int j = 0; j < 4; j++) oacc[i][j] = 0.f;

    for (int kt = 0; kt <= qi; kt++) {
        __syncthreads();
        for (int i = tid; i < 64 * 64; i += 256) {
            int c = i >> 6, e = i & 63;
            size_t g = (size_t)(b * T_ + (kt << 6) + c) * D_ + h * HD_ + e;
            float kf = g_k[g];
            uint32_t khi = f2tf(kf);
            KH[c * AQS + e] = khi;
            KL[c * AQS + e] = f2tf(kf - __uint_as_float(khi));
            VT[e * AQS + c] = f2tf(g_v[g]);
        }
        __syncthreads();

        // ---- S = Q K^T  (split tf32: hi*hi + lo*hi + hi*lo)
        float sa[4][4];
        #pragma unroll
        for (int i = 0; i < 4; i++)
            #pragma unroll
            for (int j = 0; j < 4; j++) sa[i][j] = 0.f;

        #pragma unroll
        for (int ks = 0; ks < 8; ks++) {
            int kk = ks * 8 + tig;
            uint32_t aH[4], aL[4];
            aH[0] = QH[(r0 + gid) * AQS + kk];     aH[1] = QH[(r0 + gid + 8) * AQS + kk];
            aH[2] = QH[(r0 + gid) * AQS + kk + 4]; aH[3] = QH[(r0 + gid + 8) * AQS + kk + 4];
            aL[0] = QL[(r0 + gid) * AQS + kk];     aL[1] = QL[(r0 + gid + 8) * AQS + kk];
            aL[2] = QL[(r0 + gid) * AQS + kk + 4]; aL[3] = QL[(r0 + gid + 8) * AQS + kk + 4];
            #pragma unroll
            for (int nt = 0; nt < 4; nt++) {
                int nn = n0s + nt * 8 + gid;
                uint32_t bH[2] = { KH[nn * AQS + kk], KH[nn * AQS + kk + 4] };
                uint32_t bL[2] = { KL[nn * AQS + kk], KL[nn * AQS + kk + 4] };
                mma8(sa[nt], aH, bH);
                mma8(sa[nt], aL, bH);
                mma8(sa[nt], aH, bL);
            }
        }

        // ---- scale, mask, store S
        {
            bool diag = (kt == qi);
            int ra = r0 + gid, rb = ra + 8;
            #pragma unroll
            for (int nt = 0; nt < 4; nt++) {
                int cb = n0s + nt * 8 + tig * 2;
                float v0 = sa[nt][0] * 0.125f, v1 = sa[nt][1] * 0.125f;
                float v2 = sa[nt][2] * 0.125f, v3 = sa[nt][3] * 0.125f;
                if (diag) {
                    if (cb     > ra) v0 = -1e30f;
                    if (cb + 1 > ra) v1 = -1e30f;
                    if (cb     > rb) v2 = -1e30f;
                    if (cb + 1 > rb) v3 = -1e30f;
                }
                *(float2*)&SS[ra * AQS + cb] = make_float2(v0, v1);
                *(float2*)&SS[rb * AQS + cb] = make_float2(v2, v3);
            }
        }
        __syncthreads();

        // ---- softmax (4 threads per row)
        {
            int r = tid & 63, qd = tid >> 6;
            const float* row = SS + r * AQS + qd * 16;
            float mx = -1e30f;
            #pragma unroll
            for (int j = 0; j < 16; j++) mx = fmaxf(mx, row[j]);
            PM[qd * 64 + r] = mx;
        }
        __syncthreads();
        if (tid < 64) {
            int r = tid;
            float mo = MR[r];
            float mn = fmaxf(fmaxf(PM[r], PM[64 + r]), fmaxf(PM[128 + r], PM[192 + r]));
            mn = fmaxf(mn, mo);
            MR[r] = mn;
            AR[r] = __expf(mo - mn);
        }
        __syncthreads();
        {
            int r = tid & 63, qd = tid >> 6;
            float mn = MR[r];
            float* row = SS + r * AQS + qd * 16;
            float s = 0.f;
            #pragma unroll
            for (int j = 0; j < 16; j++) {
                float p = __expf(row[j] - mn);
                row[j] = p;
                s += p;
            }
            PS[qd * 64 + r] = s;
        }
        __syncthreads();
        if (tid < 64) {
            int r = tid;
            LR[r] = LR[r] * AR[r] + PS[r] + PS[64 + r] + PS[128 + r] + PS[192 + r];
        }

        // ---- O = O*alpha + P V
        {
            float a0 = AR[r0 + gid], a1 = AR[r0 + gid + 8];
            #pragma unroll
            for (int nt = 0; nt < 4; nt++) {
                oacc[nt][0] *= a0; oacc[nt][1] *= a0;
                oacc[nt][2] *= a1; oacc[nt][3] *= a1;
            }
            #pragma unroll
            for (int ks = 0; ks < 8; ks++) {
                int kk = ks * 8 + tig;
                uint32_t af[4];
                af[0] = f2tf(SS[(r0 + gid) * AQS + kk]);
                af[1] = f2tf(SS[(r0 + gid + 8) * AQS + kk]);
                af[2] = f2tf(SS[(r0 + gid) * AQS + kk + 4]);
                af[3] = f2tf(SS[(r0 + gid + 8) * AQS + kk + 4]);
                #pragma unroll
                for (int nt = 0; nt < 4; nt++) {
                    int nn = n0s + nt * 8 + gid;
                    uint32_t bf[2] = { VT[nn * AQS + kk], VT[nn * AQS + kk + 4] };
                    mma8(oacc[nt], af, bf);
                }
            }
        }
    }

    __syncthreads();   // LR complete
    {
        float inv0 = 1.0f / LR[r0 + gid], inv1 = 1.0f / LR[r0 + gid + 8];
        #pragma unroll
        for (int nt = 0; nt < 4; nt++) {
            int cb = n0s + nt * 8 + tig * 2;
            size_t b0 = (size_t)(b * T_ + (qi << 6) + r0 + gid) * D_ + h * HD_ + cb;
            size_t b1 = (size_t)(b * T_ + (qi << 6) + r0 + gid + 8) * D_ + h * HD_ + cb;
            *(float2*)&g_ao[b0] = make_float2(oacc[nt][0] * inv0, oacc[nt][1] * inv0);
            *(float2*)&g_ao[b1] = make_float2(oacc[nt][2] * inv1, oacc[nt][3] * inv1);
        }
    }
}

// ---------------- host side ----------------------------------------------
static void launch_gemm(const float* A, const float* W, const float* bias,
                        const float* res, float* C, int M, int N, int K, int epi)
{
    dim3 grid(N / GBN, M / GBM), blk(256);
    switch (epi) {
        case 0: gemm_tc<0><<<grid, blk, GEMM_SMEM>>>(A, W, nullptr, nullptr, C, M, N, K); break;
        case 1: gemm_tc<1><<<grid, blk, GEMM_SMEM>>>(A, W, bias,    nullptr, C, M, N, K); break;
        case 3: gemm_tc<3><<<grid, blk, GEMM_SMEM>>>(A, W, bias,    nullptr, C, M, N, K); break;
        case 5: gemm_tc<5><<<grid, blk, GEMM_SMEM>>>(A, W, bias,    res,     C, M, N, K); break;
    }
}

extern "C" void kernel_launch(void* const* d_in, const int* in_sizes, int n_in,
                              void* d_out, int out_size)
{
    const int*   ctx  = (const int*)  d_in[0];
    const float* tok  = (const float*)d_in[1];
    const float* pos  = (const float*)d_in[2];
    const float* Wq   = (const float*)d_in[3];
    const float* Wk   = (const float*)d_in[4];
    const float* Wv   = (const float*)d_in[5];
    const float* Wo   = (const float*)d_in[6];
    const float* bo   = (const float*)d_in[7];
    const float* ln1s = (const float*)d_in[8];
    const float* ln1b = (const float*)d_in[9];
    const float* W1   = (const float*)d_in[10];
    const float* b1   = (const float*)d_in[11];
    const float* W2   = (const float*)d_in[12];
    const float* b2   = (const float*)d_in[13];
    const float* ln2s = (const float*)d_in[14];
    const float* ln2b = (const float*)d_in[15];
    const float* lnfs = (const float*)d_in[16];
    const float* lnfb = (const float*)d_in[17];
    const float* Wout = (const float*)d_in[18];
    const float* bout = (const float*)d_in[19];
    float* out = (float*)d_out;

    float *x, *h, *q, *k, *v, *ao, *ff;
    cudaGetSymbolAddress((void**)&x,  g_x);
    cudaGetSymbolAddress((void**)&h,  g_h);
    cudaGetSymbolAddress((void**)&q,  g_q);
    cudaGetSymbolAddress((void**)&k,  g_k);
    cudaGetSymbolAddress((void**)&v,  g_v);
    cudaGetSymbolAddress((void**)&ao, g_ao);
    cudaGetSymbolAddress((void**)&ff, g_ff);

    cudaFuncSetAttribute(attn_tc_kernel,
                         cudaFuncAttributeMaxDynamicSharedMemorySize, ATTN_SMEM);
    cudaFuncSetAttribute(gemm_tc<0>, cudaFuncAttributeMaxDynamicSharedMemorySize, GEMM_SMEM);
    cudaFuncSetAttribute(gemm_tc<1>, cudaFuncAttributeMaxDynamicSharedMemorySize, GEMM_SMEM);
    cudaFuncSetAttribute(gemm_tc<3>, cudaFuncAttributeMaxDynamicSharedMemorySize, GEMM_SMEM);
    cudaFuncSetAttribute(gemm_tc<5>, cudaFuncAttributeMaxDynamicSharedMemorySize, GEMM_SMEM);
    cudaFuncSetAttribute(gemm_qkv,   cudaFuncAttributeMaxDynamicSharedMemorySize, GEMM_SMEM);

    embed_kernel<<<BT * D_ / 1024, 256>>>(ctx, (const float4*)tok, (const float4*)pos);

    for (int l = 0; l < L_; l++) {
        ln_kernel<<<BT, 256>>>(x, ln1s + (size_t)l * D_, ln1b + (size_t)l * D_, h);
        QKVArgs p { Wq + (size_t)l * D_ * D_, Wk + (size_t)l * D_ * D_,
                    Wv + (size_t)l * D_ * D_, q, k, v };
        gemm_qkv<<<dim3(D_ / GBN, BT / GBM, 3), 256, GEMM_SMEM>>>(h, p, BT, D_, D_);
        attn_tc_kernel<<<dim3(T_ / 64, H_, Bz), 256, ATTN_SMEM>>>();
        launch_gemm(ao, Wo + (size_t)l * D_ * D_, bo + (size_t)l * D_, x, x, BT, D_, D_, 5);
        ln_kernel<<<BT, 256>>>(x, ln2s + (size_t)l * D_, ln2b + (size_t)l * D_, h);
        launch_gemm(h, W1 + (size_t)l * D_ * FF_, b1 + (size_t)l * FF_, nullptr, ff, BT, FF_, D_, 3);
        launch_gemm(ff, W2 + (size_t)l * FF_ * D_, b2 + (size_t)l * D_, x, x, BT, D_, FF_, 5);
    }
    ln_kernel<<<BT, 256>>>(x, lnfs, lnfb, h);
    launch_gemm(h, Wout, bout, nullptr, out, BT, V_, D_, 1);
}